// round 1
// baseline (speedup 1.0000x reference)
#include <cuda_runtime.h>
#include <math.h>

// R (9 floats, row-major) followed by t (3 floats). float4-aligned.
__device__ float4 g_Rt4[3];

// ---------------------------------------------------------------------------
// Kernel 1: one thread computes the SE(3) exponential map in double precision.
// ---------------------------------------------------------------------------
__global__ void se3_setup_kernel(const float* __restrict__ pose) {
    if (threadIdx.x != 0 || blockIdx.x != 0) return;

    double tau[3] = { (double)pose[0], (double)pose[1], (double)pose[2] };
    double px = (double)pose[3], py = (double)pose[4], pz = (double)pose[5];

    double theta2 = px*px + py*py + pz*pz;
    double A, B, C;
    if (theta2 < 1e-8) {
        A = 1.0 - theta2 / 6.0;
        B = 0.5 - theta2 / 24.0;
        C = 1.0 / 6.0 - theta2 / 120.0;
    } else {
        double theta = sqrt(theta2);
        double s = sin(theta), c = cos(theta);
        A = s / theta;
        B = (1.0 - c) / theta2;
        C = (theta - s) / (theta2 * theta);
    }

    double Phi[3][3] = { { 0.0, -pz,  py },
                         { pz,  0.0, -px },
                         { -py, px,  0.0 } };
    double Phi2[3][3];
    #pragma unroll
    for (int i = 0; i < 3; i++)
        #pragma unroll
        for (int j = 0; j < 3; j++) {
            double s2 = 0.0;
            #pragma unroll
            for (int k = 0; k < 3; k++) s2 += Phi[i][k] * Phi[k][j];
            Phi2[i][j] = s2;
        }

    float R[9];
    double V[3][3];
    #pragma unroll
    for (int i = 0; i < 3; i++)
        #pragma unroll
        for (int j = 0; j < 3; j++) {
            double I = (i == j) ? 1.0 : 0.0;
            R[i * 3 + j] = (float)(I + A * Phi[i][j] + B * Phi2[i][j]);
            V[i][j]     =         I + B * Phi[i][j] + C * Phi2[i][j];
        }

    float t[3];
    #pragma unroll
    for (int i = 0; i < 3; i++)
        t[i] = (float)(V[i][0] * tau[0] + V[i][1] * tau[1] + V[i][2] * tau[2]);

    float* g = (float*)g_Rt4;
    #pragma unroll
    for (int i = 0; i < 9; i++) g[i] = R[i];
    g[9] = t[0]; g[10] = t[1]; g[11] = t[2];
}

// ---------------------------------------------------------------------------
// Kernel 2: streaming transform. Each thread handles 4 points via 3 float4
// loads + 3 float4 stores (48B/thread, warp-contiguous 1536B).
// ---------------------------------------------------------------------------
__device__ __forceinline__ float3 xf(float x, float y, float z,
                                     const float* Rt) {
    float3 o;
    o.x = fmaf(Rt[0], x, fmaf(Rt[1], y, fmaf(Rt[2], z, Rt[9])));
    o.y = fmaf(Rt[3], x, fmaf(Rt[4], y, fmaf(Rt[5], z, Rt[10])));
    o.z = fmaf(Rt[6], x, fmaf(Rt[7], y, fmaf(Rt[8], z, Rt[11])));
    return o;
}

__global__ void __launch_bounds__(256)
se3_transform_kernel(const float4* __restrict__ x4, float4* __restrict__ o4,
                     int n_quads, const float* __restrict__ x_tail,
                     float* __restrict__ o_tail, int n_tail) {
    int i = blockIdx.x * blockDim.x + threadIdx.x;

    // Broadcast load of R|t (same address across warp -> 1 sector).
    float Rt[12];
    float4 a = g_Rt4[0], b = g_Rt4[1], c = g_Rt4[2];
    Rt[0]=a.x; Rt[1]=a.y; Rt[2]=a.z; Rt[3]=a.w;
    Rt[4]=b.x; Rt[5]=b.y; Rt[6]=b.z; Rt[7]=b.w;
    Rt[8]=c.x; Rt[9]=c.y; Rt[10]=c.z; Rt[11]=c.w;

    if (i < n_quads) {
        const float4* p = x4 + (size_t)3 * i;
        float4 f0 = __ldcs(p + 0);
        float4 f1 = __ldcs(p + 1);
        float4 f2 = __ldcs(p + 2);

        float3 q0 = xf(f0.x, f0.y, f0.z, Rt);
        float3 q1 = xf(f0.w, f1.x, f1.y, Rt);
        float3 q2 = xf(f1.z, f1.w, f2.x, Rt);
        float3 q3 = xf(f2.y, f2.z, f2.w, Rt);

        float4* q = o4 + (size_t)3 * i;
        __stcs(q + 0, make_float4(q0.x, q0.y, q0.z, q1.x));
        __stcs(q + 1, make_float4(q1.y, q1.z, q2.x, q2.y));
        __stcs(q + 2, make_float4(q2.z, q3.x, q3.y, q3.z));
    } else if (i == n_quads && n_tail > 0) {
        // Scalar tail (N % 4 points) — N=8388608 makes this dead code, but
        // keep it general.
        for (int k = 0; k < n_tail; k++) {
            int base = (n_quads * 4 + k) * 3;
            float3 q = xf(x_tail[base + 0], x_tail[base + 1], x_tail[base + 2], Rt);
            o_tail[base + 0] = q.x;
            o_tail[base + 1] = q.y;
            o_tail[base + 2] = q.z;
        }
    }
}

// ---------------------------------------------------------------------------
// Launch
// ---------------------------------------------------------------------------
extern "C" void kernel_launch(void* const* d_in, const int* in_sizes, int n_in,
                              void* d_out, int out_size) {
    const float* pose = (const float*)d_in[0];  // (1, 6)
    const float* x    = (const float*)d_in[1];  // (N, 3)
    float* out = (float*)d_out;

    int n_points = in_sizes[1] / 3;
    int n_quads  = n_points / 4;
    int n_tail   = n_points % 4;

    se3_setup_kernel<<<1, 1>>>(pose);

    int threads = 256;
    int total_threads = n_quads + 1;  // +1 thread covers the tail
    int blocks = (total_threads + threads - 1) / threads;
    se3_transform_kernel<<<blocks, threads>>>(
        (const float4*)x, (float4*)out, n_quads, x, out, n_tail);
}

// round 3
// speedup vs baseline: 1.0249x; 1.0249x over previous
#include <cuda_runtime.h>
#include <math.h>

// ---------------------------------------------------------------------------
// 256-bit global ops with L2 policy. ptxas requires .v8.b32/.v4.b64 with the
// L2::evict_* modifiers on this toolchain — 256-bit ops it is.
// Input (read-only, 96MB, fits in 126MB L2, re-read every graph replay) is
// pinned with evict_last; output (write-once stream) uses evict_first.
// ---------------------------------------------------------------------------
struct V8 { unsigned r0, r1, r2, r3, r4, r5, r6, r7; };

__device__ __forceinline__ V8 ldg256_el(const void* p) {
    V8 v;
    asm volatile("ld.global.nc.L2::evict_last.v8.b32 "
                 "{%0,%1,%2,%3,%4,%5,%6,%7}, [%8];"
                 : "=r"(v.r0), "=r"(v.r1), "=r"(v.r2), "=r"(v.r3),
                   "=r"(v.r4), "=r"(v.r5), "=r"(v.r6), "=r"(v.r7)
                 : "l"(p));
    return v;
}
__device__ __forceinline__ void stg256_ef(void* p, const float* g) {
    asm volatile("st.global.L2::evict_first.v8.b32 "
                 "[%0], {%1,%2,%3,%4,%5,%6,%7,%8};"
                 :: "l"(p),
                    "r"(__float_as_uint(g[0])), "r"(__float_as_uint(g[1])),
                    "r"(__float_as_uint(g[2])), "r"(__float_as_uint(g[3])),
                    "r"(__float_as_uint(g[4])), "r"(__float_as_uint(g[5])),
                    "r"(__float_as_uint(g[6])), "r"(__float_as_uint(g[7]))
                 : "memory");
}

// ---------------------------------------------------------------------------
// Fused kernel: thread 0 of each block computes the SE(3) exp map in fp32
// (rel_err budget 1e-3; this path contributes ~1e-6), broadcasts R|t via
// smem. Each thread then transforms 8 points via 3 front-batched 256-bit
// loads + 3 stores (96B/thread).
// ---------------------------------------------------------------------------
__global__ void __launch_bounds__(256)
se3_fused_kernel(const float* __restrict__ pose,
                 const char* __restrict__ xb, char* __restrict__ ob,
                 int n_oct,
                 const float* __restrict__ x_tail, float* __restrict__ o_tail,
                 int n_tail) {
    __shared__ float sRt[12];

    if (threadIdx.x == 0) {
        float tx = pose[0], ty = pose[1], tz = pose[2];
        float px = pose[3], py = pose[4], pz = pose[5];
        float th2 = px * px + py * py + pz * pz;
        float A, B, C;
        if (th2 < 1e-8f) {
            A = 1.0f - th2 / 6.0f;
            B = 0.5f - th2 / 24.0f;
            C = 1.0f / 6.0f - th2 / 120.0f;
        } else {
            float th = sqrtf(th2);
            float s = sinf(th), c = cosf(th);
            A = s / th;
            B = (1.0f - c) / th2;
            C = (th - s) / (th2 * th);
        }
        // Phi^2 = phi*phi^T - th2*I (skew-symmetric identity)
        float R[9], V[9];
        R[0] = 1.0f + B * (px * px - th2);
        R[1] = -A * pz + B * px * py;
        R[2] =  A * py + B * px * pz;
        R[3] =  A * pz + B * px * py;
        R[4] = 1.0f + B * (py * py - th2);
        R[5] = -A * px + B * py * pz;
        R[6] = -A * py + B * px * pz;
        R[7] =  A * px + B * py * pz;
        R[8] = 1.0f + B * (pz * pz - th2);

        V[0] = 1.0f + C * (px * px - th2);
        V[1] = -B * pz + C * px * py;
        V[2] =  B * py + C * px * pz;
        V[3] =  B * pz + C * px * py;
        V[4] = 1.0f + C * (py * py - th2);
        V[5] = -B * px + C * py * pz;
        V[6] = -B * py + C * px * pz;
        V[7] =  B * px + C * py * pz;
        V[8] = 1.0f + C * (pz * pz - th2);

        #pragma unroll
        for (int k = 0; k < 9; k++) sRt[k] = R[k];
        sRt[9]  = V[0] * tx + V[1] * ty + V[2] * tz;
        sRt[10] = V[3] * tx + V[4] * ty + V[5] * tz;
        sRt[11] = V[6] * tx + V[7] * ty + V[8] * tz;
    }
    __syncthreads();

    float Rt[12];
    #pragma unroll
    for (int k = 0; k < 12; k++) Rt[k] = sRt[k];

    int i = blockIdx.x * blockDim.x + threadIdx.x;

    if (i < n_oct) {
        const char* p = xb + (size_t)96 * i;
        // Front-batch the 3 × 256-bit loads.
        V8 a = ldg256_el(p);
        V8 b = ldg256_el(p + 32);
        V8 c = ldg256_el(p + 64);

        float f[24] = {
            __uint_as_float(a.r0), __uint_as_float(a.r1), __uint_as_float(a.r2),
            __uint_as_float(a.r3), __uint_as_float(a.r4), __uint_as_float(a.r5),
            __uint_as_float(a.r6), __uint_as_float(a.r7),
            __uint_as_float(b.r0), __uint_as_float(b.r1), __uint_as_float(b.r2),
            __uint_as_float(b.r3), __uint_as_float(b.r4), __uint_as_float(b.r5),
            __uint_as_float(b.r6), __uint_as_float(b.r7),
            __uint_as_float(c.r0), __uint_as_float(c.r1), __uint_as_float(c.r2),
            __uint_as_float(c.r3), __uint_as_float(c.r4), __uint_as_float(c.r5),
            __uint_as_float(c.r6), __uint_as_float(c.r7)
        };

        float g[24];
        #pragma unroll
        for (int k = 0; k < 8; k++) {
            float X = f[3 * k], Y = f[3 * k + 1], Z = f[3 * k + 2];
            g[3 * k + 0] = fmaf(Rt[0], X, fmaf(Rt[1], Y, fmaf(Rt[2], Z, Rt[9])));
            g[3 * k + 1] = fmaf(Rt[3], X, fmaf(Rt[4], Y, fmaf(Rt[5], Z, Rt[10])));
            g[3 * k + 2] = fmaf(Rt[6], X, fmaf(Rt[7], Y, fmaf(Rt[8], Z, Rt[11])));
        }

        char* q = ob + (size_t)96 * i;
        stg256_ef(q,      g);
        stg256_ef(q + 32, g + 8);
        stg256_ef(q + 64, g + 16);
    } else if (i == n_oct && n_tail > 0) {
        // Scalar tail (N % 8 points); dead for N = 8388608 but kept general.
        for (int k = 0; k < n_tail; k++) {
            int base = (n_oct * 8 + k) * 3;
            float X = x_tail[base + 0], Y = x_tail[base + 1], Z = x_tail[base + 2];
            o_tail[base + 0] = fmaf(Rt[0], X, fmaf(Rt[1], Y, fmaf(Rt[2], Z, Rt[9])));
            o_tail[base + 1] = fmaf(Rt[3], X, fmaf(Rt[4], Y, fmaf(Rt[5], Z, Rt[10])));
            o_tail[base + 2] = fmaf(Rt[6], X, fmaf(Rt[7], Y, fmaf(Rt[8], Z, Rt[11])));
        }
    }
}

// ---------------------------------------------------------------------------
// Launch: single fused kernel.
// ---------------------------------------------------------------------------
extern "C" void kernel_launch(void* const* d_in, const int* in_sizes, int n_in,
                              void* d_out, int out_size) {
    const float* pose = (const float*)d_in[0];  // (1, 6)
    const float* x    = (const float*)d_in[1];  // (N, 3)
    float* out = (float*)d_out;

    int n_points = in_sizes[1] / 3;
    int n_oct    = n_points / 8;
    int n_tail   = n_points % 8;

    int threads = 256;
    int total_threads = n_oct + 1;  // +1 thread covers the tail
    int blocks = (total_threads + threads - 1) / threads;

    se3_fused_kernel<<<blocks, threads>>>(
        pose, (const char*)x, (char*)out, n_oct, x, out, n_tail);
}